// round 6
// baseline (speedup 1.0000x reference)
#include <cuda_runtime.h>
#include <cstdint>

// MultiVariatePoly: out[n] = sum_{i,j,k} W[i*100+j*10+k] * Px_i * Py_j * Pz_k + b
// DIM=3, ORDER=9. 2 points per thread share each W load (halved LDS traffic);
// the i-range is split across two half-blocks (i in [0,5) / [5,10)) to double
// resident warps; partials combined through shared memory.
// All inner math in packed fp32 (fma.rn.f32x2).
// (Resubmission of R5 — previous round failed on container infra, no data.)

#define NP1 10
#define NFEAT 1000
#define IHALF 5

typedef unsigned long long u64;

__device__ __forceinline__ u64 f2_pack(float lo, float hi) {
    u64 d; asm("mov.b64 %0, {%1, %2};" : "=l"(d) : "f"(lo), "f"(hi)); return d;
}
__device__ __forceinline__ u64 f2_splat(float s) {
    u64 d; asm("mov.b64 %0, {%1, %1};" : "=l"(d) : "f"(s)); return d;
}
__device__ __forceinline__ void f2_unpack(u64 v, float& lo, float& hi) {
    asm("mov.b64 {%0, %1}, %2;" : "=f"(lo), "=f"(hi) : "l"(v));
}
__device__ __forceinline__ u64 f2_fma(u64 a, u64 b, u64 c) {
    u64 d; asm("fma.rn.f32x2 %0, %1, %2, %3;" : "=l"(d) : "l"(a), "l"(b), "l"(c)); return d;
}
__device__ __forceinline__ u64 f2_mul(u64 a, u64 b) {
    u64 d; asm("mul.rn.f32x2 %0, %1, %2;" : "=l"(d) : "l"(a), "l"(b)); return d;
}

// Scalar Legendre recurrence, constants folded at compile time.
__device__ __forceinline__ void legendre1(float x, float P[NP1]) {
    P[0] = 1.0f;
    P[1] = x;
#pragma unroll
    for (int k = 1; k < NP1 - 1; k++) {
        const float c1 = (float)(2 * k + 1) / (float)(k + 1);
        const float c2 = -(float)k / (float)(k + 1);
        P[k + 1] = c1 * x * P[k] + c2 * P[k - 1];
    }
}

__global__ void __launch_bounds__(256, 2)
poly_kernel(const float* __restrict__ x, const float* __restrict__ W,
            const float* __restrict__ bptr, float* __restrict__ out, int N) {
    __shared__ __align__(16) float sW[NFEAT];   // 4 KB
    __shared__ float2 sPart[256];               // 2 KB partial results

    {
        const float4* Wv = reinterpret_cast<const float4*>(W);
        float4* sWv = reinterpret_cast<float4*>(sW);
        for (int e = threadIdx.x; e < NFEAT / 4; e += blockDim.x) sWv[e] = Wv[e];
    }
    __syncthreads();

    // Block covers 256 consecutive points. Lane role:
    //   pt  = threadIdx.x & 127  -> owns points (base+pt, base+pt+128)
    //   hi  = threadIdx.x >> 7   -> i-range [5,10) if hi else [0,5)
    int lane = threadIdx.x & 127;
    int hi = threadIdx.x >> 7;
    int base = blockIdx.x * 256;
    int pA = base + lane;
    int pB = pA + 128;
    int pBc = (pB < N) ? pB : pA;  // degenerate duplicate for tail

    float xA0 = x[3 * pA + 0], xA1 = x[3 * pA + 1], xA2 = x[3 * pA + 2];
    float xB0 = x[3 * pBc + 0], xB1 = x[3 * pBc + 1], xB2 = x[3 * pBc + 2];

    float PxA[NP1], PyA[NP1], PzA[NP1];
    float PxB[NP1], PyB[NP1], PzB[NP1];
    legendre1(xA0, PxA); legendre1(xA1, PyA); legendre1(xA2, PzA);
    legendre1(xB0, PxB); legendre1(xB1, PyB); legendre1(xB2, PzB);

    u64 PzpA[NP1 / 2], PzpB[NP1 / 2];
#pragma unroll
    for (int kk = 0; kk < NP1 / 2; kk++) {
        PzpA[kk] = f2_pack(PzA[2 * kk], PzA[2 * kk + 1]);
        PzpB[kk] = f2_pack(PzB[2 * kk], PzB[2 * kk + 1]);
    }

    const ulonglong2* sWq = reinterpret_cast<const ulonglong2*>(sW);
    int ibase = hi * IHALF;

    u64 rA0 = 0ull, rA1 = 0ull, rB0 = 0ull, rB1 = 0ull;
#pragma unroll
    for (int ii = 0; ii < IHALF; ii++) {
        int i = ibase + ii;
        const ulonglong2* row = sWq + i * 25;  // i*100 floats
        u64 sA0 = 0ull, sA1 = 0ull, sB0 = 0ull, sB1 = 0ull;
#pragma unroll
        for (int jj = 0; jj < NP1 / 2; jj++) {
            // rows j=2jj, 2jj+1: 20 floats = 5 ulonglong2 (10 f32x2 W pairs)
            ulonglong2 w0 = row[jj * 5 + 0];
            ulonglong2 w1 = row[jj * 5 + 1];
            ulonglong2 w2 = row[jj * 5 + 2];
            ulonglong2 w3 = row[jj * 5 + 3];
            ulonglong2 w4 = row[jj * 5 + 4];

            // 4 independent FFMA2 chains per point-pair
            u64 tA0 = f2_mul(w0.x, PzpA[0]);
            u64 tB0 = f2_mul(w0.x, PzpB[0]);
            u64 tA1 = f2_mul(w2.y, PzpA[0]);
            u64 tB1 = f2_mul(w2.y, PzpB[0]);
            tA0 = f2_fma(w0.y, PzpA[1], tA0);
            tB0 = f2_fma(w0.y, PzpB[1], tB0);
            tA1 = f2_fma(w3.x, PzpA[1], tA1);
            tB1 = f2_fma(w3.x, PzpB[1], tB1);
            tA0 = f2_fma(w1.x, PzpA[2], tA0);
            tB0 = f2_fma(w1.x, PzpB[2], tB0);
            tA1 = f2_fma(w3.y, PzpA[2], tA1);
            tB1 = f2_fma(w3.y, PzpB[2], tB1);
            tA0 = f2_fma(w1.y, PzpA[3], tA0);
            tB0 = f2_fma(w1.y, PzpB[3], tB0);
            tA1 = f2_fma(w4.x, PzpA[3], tA1);
            tB1 = f2_fma(w4.x, PzpB[3], tB1);
            tA0 = f2_fma(w2.x, PzpA[4], tA0);
            tB0 = f2_fma(w2.x, PzpB[4], tB0);
            tA1 = f2_fma(w4.y, PzpA[4], tA1);
            tB1 = f2_fma(w4.y, PzpB[4], tB1);

            u64 pyA0 = f2_splat(PyA[2 * jj + 0]);
            u64 pyA1 = f2_splat(PyA[2 * jj + 1]);
            u64 pyB0 = f2_splat(PyB[2 * jj + 0]);
            u64 pyB1 = f2_splat(PyB[2 * jj + 1]);
            sA0 = f2_fma(tA0, pyA0, sA0);
            sA1 = f2_fma(tA1, pyA1, sA1);
            sB0 = f2_fma(tB0, pyB0, sB0);
            sB1 = f2_fma(tB1, pyB1, sB1);
        }
        u64 pxA = f2_splat(PxA[i]);
        u64 pxB = f2_splat(PxB[i]);
        rA0 = f2_fma(sA0, pxA, rA0);
        rA1 = f2_fma(sA1, pxA, rA1);
        rB0 = f2_fma(sB0, pxB, rB0);
        rB1 = f2_fma(sB1, pxB, rB1);
    }

    // Reduce packed accumulators to two scalar partials.
    float a0, a1, a2, a3, c0, c1, c2, c3;
    f2_unpack(rA0, a0, a1);
    f2_unpack(rA1, a2, a3);
    f2_unpack(rB0, c0, c1);
    f2_unpack(rB1, c2, c3);
    float partA = (a0 + a1) + (a2 + a3);
    float partB = (c0 + c1) + (c2 + c3);

    sPart[threadIdx.x] = make_float2(partA, partB);
    __syncthreads();

    if (hi == 0) {
        float2 other = sPart[threadIdx.x + 128];
        float bb = *bptr;
        out[pA] = partA + other.x + bb;
        if (pB < N) out[pB] = partB + other.y + bb;
    }
}

extern "C" void kernel_launch(void* const* d_in, const int* in_sizes, int n_in,
                              void* d_out, int out_size) {
    // Identify inputs by size: b has 1 element, x is the largest, W is the rest.
    int ib = -1, ix = -1, iw = -1;
    int max_sz = -1;
    for (int i = 0; i < n_in; i++) {
        if (in_sizes[i] == 1 && ib < 0) ib = i;
        else if (in_sizes[i] > max_sz) { max_sz = in_sizes[i]; ix = i; }
    }
    for (int i = 0; i < n_in; i++) {
        if (i != ib && i != ix) { iw = i; break; }
    }

    const float* x = (const float*)d_in[ix];
    const float* W = (const float*)d_in[iw];
    const float* b = (const float*)d_in[ib];
    float* out = (float*)d_out;

    int N = in_sizes[ix] / 3;
    int block = 256;
    int grid = (N + 255) / 256;  // 256 points per block (2 pts/thread, i-split)

    poly_kernel<<<grid, block>>>(x, W, b, out, N);
}

// round 7
// speedup vs baseline: 1.0287x; 1.0287x over previous
#include <cuda_runtime.h>
#include <cstdint>

// MultiVariatePoly: out[n] = sum_{i,j,k} W[i*100+j*10+k] * Px_i * Py_j * Pz_k + b
// DIM=3, ORDER=9. TWO points per thread sharing each W load (R4 structure),
// but block=64 / grid=782 to fix wave quantization (5.28 blocks/SM, +-9%
// imbalance instead of 2.64, +-33%). All inner math in fma.rn.f32x2.

#define NP1 10
#define NFEAT 1000

typedef unsigned long long u64;

__device__ __forceinline__ u64 f2_pack(float lo, float hi) {
    u64 d; asm("mov.b64 %0, {%1, %2};" : "=l"(d) : "f"(lo), "f"(hi)); return d;
}
__device__ __forceinline__ u64 f2_splat(float s) {
    u64 d; asm("mov.b64 %0, {%1, %1};" : "=l"(d) : "f"(s)); return d;
}
__device__ __forceinline__ void f2_unpack(u64 v, float& lo, float& hi) {
    asm("mov.b64 {%0, %1}, %2;" : "=f"(lo), "=f"(hi) : "l"(v));
}
__device__ __forceinline__ u64 f2_fma(u64 a, u64 b, u64 c) {
    u64 d; asm("fma.rn.f32x2 %0, %1, %2, %3;" : "=l"(d) : "l"(a), "l"(b), "l"(c)); return d;
}
__device__ __forceinline__ u64 f2_mul(u64 a, u64 b) {
    u64 d; asm("mul.rn.f32x2 %0, %1, %2;" : "=l"(d) : "l"(a), "l"(b)); return d;
}

// Scalar Legendre recurrence, constants folded at compile time.
__device__ __forceinline__ void legendre1(float x, float P[NP1]) {
    P[0] = 1.0f;
    P[1] = x;
#pragma unroll
    for (int k = 1; k < NP1 - 1; k++) {
        const float c1 = (float)(2 * k + 1) / (float)(k + 1);
        const float c2 = -(float)k / (float)(k + 1);
        P[k + 1] = c1 * x * P[k] + c2 * P[k - 1];
    }
}

__global__ void __launch_bounds__(64, 8)
poly_kernel(const float* __restrict__ x, const float* __restrict__ W,
            const float* __restrict__ bptr, float* __restrict__ out, int N) {
    __shared__ __align__(16) float sW[NFEAT];  // 4 KB

    {
        const float4* Wv = reinterpret_cast<const float4*>(W);
        float4* sWv = reinterpret_cast<float4*>(sW);
        for (int e = threadIdx.x; e < NFEAT / 4; e += blockDim.x) sWv[e] = Wv[e];
    }

    float bb = *bptr;  // hoist off the epilogue critical path
    __syncthreads();

    // Each block covers 128 consecutive points: thread t owns (base+t, base+t+64).
    int base = blockIdx.x * 128;
    int pA = base + threadIdx.x;
    int pB = pA + 64;
    if (pA >= N) return;
    int pBc = (pB < N) ? pB : pA;  // degenerate duplicate for the tail

    float xA0 = x[3 * pA + 0], xA1 = x[3 * pA + 1], xA2 = x[3 * pA + 2];
    float xB0 = x[3 * pBc + 0], xB1 = x[3 * pBc + 1], xB2 = x[3 * pBc + 2];

    float PxA[NP1], PyA[NP1], PzA[NP1];
    float PxB[NP1], PyB[NP1], PzB[NP1];
    legendre1(xA0, PxA); legendre1(xA1, PyA); legendre1(xA2, PzA);
    legendre1(xB0, PxB); legendre1(xB1, PyB); legendre1(xB2, PzB);

    // Pz packed as (even,odd) k pairs — the only resident packed polys.
    u64 PzpA[NP1 / 2], PzpB[NP1 / 2];
#pragma unroll
    for (int kk = 0; kk < NP1 / 2; kk++) {
        PzpA[kk] = f2_pack(PzA[2 * kk], PzA[2 * kk + 1]);
        PzpB[kk] = f2_pack(PzB[2 * kk], PzB[2 * kk + 1]);
    }

    const ulonglong2* sWq = reinterpret_cast<const ulonglong2*>(sW);

    u64 rA0 = 0ull, rA1 = 0ull, rB0 = 0ull, rB1 = 0ull;
#pragma unroll
    for (int i = 0; i < NP1; i++) {
        const ulonglong2* row = sWq + i * 25;  // i*100 floats
        u64 sA0 = 0ull, sA1 = 0ull, sB0 = 0ull, sB1 = 0ull;
#pragma unroll
        for (int jj = 0; jj < NP1 / 2; jj++) {
            // rows j=2jj, 2jj+1: 20 floats = 5 ulonglong2 (10 f32x2 W pairs)
            ulonglong2 w0 = row[jj * 5 + 0];
            ulonglong2 w1 = row[jj * 5 + 1];
            ulonglong2 w2 = row[jj * 5 + 2];
            ulonglong2 w3 = row[jj * 5 + 3];
            ulonglong2 w4 = row[jj * 5 + 4];

            // 4 independent FFMA2 chains per point-pair
            u64 tA0 = f2_mul(w0.x, PzpA[0]);
            u64 tB0 = f2_mul(w0.x, PzpB[0]);
            u64 tA1 = f2_mul(w2.y, PzpA[0]);
            u64 tB1 = f2_mul(w2.y, PzpB[0]);
            tA0 = f2_fma(w0.y, PzpA[1], tA0);
            tB0 = f2_fma(w0.y, PzpB[1], tB0);
            tA1 = f2_fma(w3.x, PzpA[1], tA1);
            tB1 = f2_fma(w3.x, PzpB[1], tB1);
            tA0 = f2_fma(w1.x, PzpA[2], tA0);
            tB0 = f2_fma(w1.x, PzpB[2], tB0);
            tA1 = f2_fma(w3.y, PzpA[2], tA1);
            tB1 = f2_fma(w3.y, PzpB[2], tB1);
            tA0 = f2_fma(w1.y, PzpA[3], tA0);
            tB0 = f2_fma(w1.y, PzpB[3], tB0);
            tA1 = f2_fma(w4.x, PzpA[3], tA1);
            tB1 = f2_fma(w4.x, PzpB[3], tB1);
            tA0 = f2_fma(w2.x, PzpA[4], tA0);
            tB0 = f2_fma(w2.x, PzpB[4], tB0);
            tA1 = f2_fma(w4.y, PzpA[4], tA1);
            tB1 = f2_fma(w4.y, PzpB[4], tB1);

            // fold into s with on-the-fly Py splats (ALU pipe has headroom)
            u64 pyA0 = f2_splat(PyA[2 * jj + 0]);
            u64 pyA1 = f2_splat(PyA[2 * jj + 1]);
            u64 pyB0 = f2_splat(PyB[2 * jj + 0]);
            u64 pyB1 = f2_splat(PyB[2 * jj + 1]);
            sA0 = f2_fma(tA0, pyA0, sA0);
            sA1 = f2_fma(tA1, pyA1, sA1);
            sB0 = f2_fma(tB0, pyB0, sB0);
            sB1 = f2_fma(tB1, pyB1, sB1);
        }
        u64 pxA = f2_splat(PxA[i]);
        u64 pxB = f2_splat(PxB[i]);
        rA0 = f2_fma(sA0, pxA, rA0);
        rA1 = f2_fma(sA1, pxA, rA1);
        rB0 = f2_fma(sB0, pxB, rB0);
        rB1 = f2_fma(sB1, pxB, rB1);
    }

    float a0, a1, a2, a3, c0, c1, c2, c3;
    f2_unpack(rA0, a0, a1);
    f2_unpack(rA1, a2, a3);
    f2_unpack(rB0, c0, c1);
    f2_unpack(rB1, c2, c3);

    out[pA] = (a0 + a1) + (a2 + a3) + bb;
    if (pB < N) out[pB] = (c0 + c1) + (c2 + c3) + bb;
}

extern "C" void kernel_launch(void* const* d_in, const int* in_sizes, int n_in,
                              void* d_out, int out_size) {
    // Identify inputs by size: b has 1 element, x is the largest, W is the rest.
    int ib = -1, ix = -1, iw = -1;
    int max_sz = -1;
    for (int i = 0; i < n_in; i++) {
        if (in_sizes[i] == 1 && ib < 0) ib = i;
        else if (in_sizes[i] > max_sz) { max_sz = in_sizes[i]; ix = i; }
    }
    for (int i = 0; i < n_in; i++) {
        if (i != ib && i != ix) { iw = i; break; }
    }

    const float* x = (const float*)d_in[ix];
    const float* W = (const float*)d_in[iw];
    const float* b = (const float*)d_in[ib];
    float* out = (float*)d_out;

    int N = in_sizes[ix] / 3;
    int block = 64;
    int grid = (N + 2 * block - 1) / (2 * block);  // 128 points per block

    poly_kernel<<<grid, block>>>(x, W, b, out, N);
}